// round 8
// baseline (speedup 1.0000x reference)
#include <cuda_runtime.h>
#include <cuda_bf16.h>
#include <cstdint>

#define NTOK 65
#define MTOK 129
#define NHEAD 16
#define HDIM 64
#define CDIM 1024

// fp32 intermediates
__device__ float g_q [512 * NTOK * CDIM];
__device__ float g_kv[512 * MTOK * 2 * CDIM];
__device__ float g_ao[512 * NTOK * CDIM];
// tf32-rounded, k-permuted weights [N][perm(K)]
__device__ float g_wqt [CDIM * CDIM];
__device__ float g_wkvt[2 * CDIM * CDIM];
__device__ float g_wpt [CDIM * CDIM];

__device__ __forceinline__ unsigned f2tf32(float x) {
    unsigned r;
    asm("cvt.rna.tf32.f32 %0, %1;" : "=r"(r) : "f"(x));
    return r;
}
__device__ __forceinline__ void cp16s(uint32_t s, const float* g) {
    asm volatile("cp.async.cg.shared.global [%0], [%1], 16;"
                 :: "r"(s), "l"(g) : "memory");
}
__device__ __forceinline__ uint32_t smem_u32(const void* p) {
    uint32_t a;
    asm("{ .reg .u64 t; cvta.to.shared.u64 t, %1; cvt.u32.u64 %0, t; }"
        : "=r"(a) : "l"(p));
    return a;
}

// ---------------------------------------------------------------------------
// W[K][N] fp32 -> Wt[N][perm(K)] tf32-rounded; perm within 8-groups:
// p(k) = (k&~7)|((k&3)<<1)|((k>>2)&1)
// ---------------------------------------------------------------------------
__global__ __launch_bounds__(256) void transpose_tf32_perm(
    const float* __restrict__ W, float* __restrict__ Wt, int K, int N)
{
    __shared__ float t[32][33];
    const int n0 = blockIdx.x * 32, k0 = blockIdx.y * 32;
    const int tx = threadIdx.x & 31, ty = threadIdx.x >> 5;
    #pragma unroll
    for (int i = 0; i < 4; i++)
        t[ty + 8 * i][tx] = W[(size_t)(k0 + ty + 8 * i) * N + n0 + tx];
    __syncthreads();
    const int pk = (tx & ~7) | ((tx & 3) << 1) | ((tx >> 2) & 1);
    #pragma unroll
    for (int i = 0; i < 4; i++)
        Wt[(size_t)(n0 + ty + 8 * i) * K + k0 + pk] =
            __uint_as_float(f2tf32(t[tx][ty + 8 * i]));
}

// ---------------------------------------------------------------------------
// tf32 mma.sync GEMM: C[M,N] = A[M,K] @ Bt[N,K]^T + bias[N]
// Block tile 128x128, 8 warps (2M x 4N), warp tile 64x32, K-tile 32.
// A: raw fp32 LDG -> cvt.rna+perm -> STS (fused, double-buffered regs).
// B: pre-rounded/permuted weights via cp.async.
// Smem row stride 40 words: LDS.64 fragment reads conflict-free. 2 CTA/SM.
// ---------------------------------------------------------------------------
#define GS 40
#define TILE_W (128 * GS)              // 5120 words per operand
#define STAGE_W (2 * TILE_W)           // A + B per stage

__global__ __launch_bounds__(256, 2) void gemm_mma(
    const float* __restrict__ A, const float* __restrict__ Bt,
    const float* __restrict__ bias, float* __restrict__ C,
    int M, int N, int K)
{
    extern __shared__ float smg[];     // [2][STAGE_W] = 81920 B

    const int tid  = threadIdx.x;
    const int lane = tid & 31;
    const int warp = tid >> 5;
    const int wm   = warp >> 2;        // 0..1
    const int wn   = warp & 3;         // 0..3
    const int g    = lane >> 2;        // 0..7
    const int t    = lane & 3;         // 0..3

    const int bn = blockIdx.x, bm = blockIdx.y;
    const float* Ag = A  + (size_t)bm * 128 * K;
    const float* Bg = Bt + (size_t)bn * 128 * K;
    const uint32_t sb = smem_u32(smg);

    // A staging: thread owns row arow, 16 consecutive k at akh
    const int arow = tid >> 1;
    const int akh  = (tid & 1) * 16;
    const float* aptr = Ag + (size_t)arow * K + akh;

    float4 r0, r1, r2, r3;
    auto ldgA = [&](int kt) {
        const float* p = aptr + kt;
        r0 = *(const float4*)(p);
        r1 = *(const float4*)(p + 4);
        r2 = *(const float4*)(p + 8);
        r3 = *(const float4*)(p + 12);
    };
    auto stsA = [&](int s) {           // cvt.rna + perm, 4x STS.128
        float* dst = smg + s * STAGE_W + arow * GS + akh;
        uint4 w;
        w.x = f2tf32(r0.x); w.y = f2tf32(r1.x); w.z = f2tf32(r0.y); w.w = f2tf32(r1.y);
        *(uint4*)(dst)      = w;
        w.x = f2tf32(r0.z); w.y = f2tf32(r1.z); w.z = f2tf32(r0.w); w.w = f2tf32(r1.w);
        *(uint4*)(dst + 4)  = w;
        w.x = f2tf32(r2.x); w.y = f2tf32(r3.x); w.z = f2tf32(r2.y); w.w = f2tf32(r3.y);
        *(uint4*)(dst + 8)  = w;
        w.x = f2tf32(r2.z); w.y = f2tf32(r3.z); w.z = f2tf32(r2.w); w.w = f2tf32(r3.w);
        *(uint4*)(dst + 12) = w;
    };
    auto cpB = [&](int kt, int s) {    // 128 rows x 8 chunks = 1024 cp16
        const uint32_t base = sb + (s * STAGE_W + TILE_W) * 4;
        #pragma unroll
        for (int it = 0; it < 4; it++) {
            int idx = tid + it * 256;
            int row = idx >> 3, c = idx & 7;
            cp16s(base + (row * GS + c * 4) * 4,
                  Bg + (size_t)row * K + kt + c * 4);
        }
        asm volatile("cp.async.commit_group;" ::: "memory");
    };

    float acc[4][4][4];
    #pragma unroll
    for (int i = 0; i < 4; i++)
        #pragma unroll
        for (int j = 0; j < 4; j++)
            #pragma unroll
            for (int r = 0; r < 4; r++) acc[i][j][r] = 0.f;

    const int NT = K >> 5;
    // prologue
    ldgA(0);
    cpB(0, 0);
    stsA(0);
    if (NT > 1) ldgA(32);
    asm volatile("cp.async.wait_group 0;" ::: "memory");
    __syncthreads();

    for (int ti = 0; ti < NT; ti++) {
        const int cur = ti & 1;
        if (ti + 1 < NT) {
            stsA(cur ^ 1);             // regs hold tile ti+1
            cpB((ti + 1) << 5, cur ^ 1);
            if (ti + 2 < NT) ldgA((ti + 2) << 5);
        }

        const float* As = smg + cur * STAGE_W;
        const float* Bs = As + TILE_W;
        #pragma unroll
        for (int ks = 0; ks < 4; ks++) {
            const int k0 = ks * 8 + 2 * t;
            unsigned af[4][4];
            #pragma unroll
            for (int i = 0; i < 4; i++) {
                int r = wm * 64 + i * 16 + g;
                uint2 lo = *(const uint2*)(As + r * GS + k0);
                uint2 hi = *(const uint2*)(As + (r + 8) * GS + k0);
                af[i][0] = lo.x; af[i][2] = lo.y;
                af[i][1] = hi.x; af[i][3] = hi.y;
            }
            unsigned bf[4][2];
            #pragma unroll
            for (int j = 0; j < 4; j++) {
                int n = wn * 32 + j * 8 + g;
                uint2 bb = *(const uint2*)(Bs + n * GS + k0);
                bf[j][0] = bb.x; bf[j][1] = bb.y;
            }
            #pragma unroll
            for (int i = 0; i < 4; i++)
                #pragma unroll
                for (int j = 0; j < 4; j++) {
                    asm volatile(
                        "mma.sync.aligned.m16n8k8.row.col.f32.tf32.tf32.f32 "
                        "{%0,%1,%2,%3}, {%4,%5,%6,%7}, {%8,%9}, {%0,%1,%2,%3};"
                        : "+f"(acc[i][j][0]), "+f"(acc[i][j][1]),
                          "+f"(acc[i][j][2]), "+f"(acc[i][j][3])
                        : "r"(af[i][0]), "r"(af[i][1]), "r"(af[i][2]), "r"(af[i][3]),
                          "r"(bf[j][0]), "r"(bf[j][1]));
                }
        }

        if (ti + 1 < NT)
            asm volatile("cp.async.wait_group 0;" ::: "memory");
        __syncthreads();
    }

    #pragma unroll
    for (int i = 0; i < 4; i++) {
        int row0 = bm * 128 + wm * 64 + i * 16 + g;
        #pragma unroll
        for (int j = 0; j < 4; j++) {
            int col = bn * 128 + wn * 32 + j * 8 + t * 2;
            float b0 = bias[col], b1 = bias[col + 1];
            float2 v0 = make_float2(acc[i][j][0] + b0, acc[i][j][1] + b1);
            float2 v1 = make_float2(acc[i][j][2] + b0, acc[i][j][3] + b1);
            *(float2*)(C + (size_t)row0 * N + col)       = v0;
            *(float2*)(C + (size_t)(row0 + 8) * N + col) = v1;
        }
    }
}

// ---------------------------------------------------------------------------
// Fused attention (unchanged; raw fp32 output — P GEMM rounds during staging)
// ---------------------------------------------------------------------------
#define KSTR 68
#define VSTR 132
#define PSTR 132

__global__ __launch_bounds__(256) void attn_kernel(
    const float* __restrict__ q, const float* __restrict__ kv,
    const int* __restrict__ mask_l,
    const int* __restrict__ mask_r,
    const int* __restrict__ nW_ptr,
    const float* __restrict__ rel_table,
    const float* __restrict__ cls_self,
    const float* __restrict__ cls_up,
    const float* __restrict__ cls_down,
    float* __restrict__ ao)
{
    const int h = blockIdx.x;
    const int b = blockIdx.y;
    const int tid = threadIdx.x;
    const int lane = tid & 31;
    const int warp = tid >> 5;

    extern __shared__ float sm[];
    float* Ks = sm;
    float* Vt = Ks + MTOK * KSTR;
    float* Qs = Vt + HDIM * VSTR;
    float* Ps = Qs + NTOK * HDIM;
    float* tb = Ps + 8 * 2 * PSTR;

    for (int i = tid; i < 191; i += 256) tb[i] = rel_table[i * NHEAD + h];
    if (tid == 0) tb[191] = cls_self[h];
    for (int i = tid; i < 128; i += 256) tb[192 + i] = cls_up[h * (MTOK - 1) + i];
    for (int i = tid; i < 64; i += 256) tb[320 + i] = cls_down[h * (NTOK - 1) + i];

    const float* kvb = kv + (size_t)b * MTOK * 2 * CDIM + h * HDIM;
    for (int idx = tid; idx < MTOK * 16; idx += 256) {
        int m = idx >> 4, d4 = (idx & 15) << 2;
        float4 kk = *(const float4*)(kvb + (size_t)m * 2048 + d4);
        *(float4*)(Ks + m * KSTR + d4) = kk;
        float4 vv = *(const float4*)(kvb + (size_t)m * 2048 + CDIM + d4);
        Vt[(d4 + 0) * VSTR + m] = vv.x;
        Vt[(d4 + 1) * VSTR + m] = vv.y;
        Vt[(d4 + 2) * VSTR + m] = vv.z;
        Vt[(d4 + 3) * VSTR + m] = vv.w;
    }
    const float* qb = q + (size_t)b * NTOK * CDIM + h * HDIM;
    for (int idx = tid; idx < NTOK * 16; idx += 256) {
        int n = idx >> 4, d4 = (idx & 15) << 2;
        *(float4*)(Qs + n * HDIM + d4) = *(const float4*)(qb + (size_t)n * CDIM + d4);
    }
    __syncthreads();

    const int nW = *nW_ptr;
    const int mc = (nW < 2) ? nW : 2;
    const int w = b % nW;
    const bool use_l = (w < mc);
    const bool use_r = (w >= nW - mc);
    const int* ml = mask_l + (size_t)w * NTOK * MTOK;
    const int* mr = mask_r + (size_t)(2 - mc + (w - (nW - mc))) * NTOK * MTOK;

    const float scale = 0.125f;
    const float NEG = -3.402823466e38f;

    for (int n0 = warp * 2; n0 < NTOK; n0 += 16) {
        const bool two = (n0 + 1 < NTOK);
        const int n1 = two ? n0 + 1 : n0;
        const int nm = (lane == 0) ? 5 : 4;
        float s0[5], s1[5];
        const float4* q0 = (const float4*)(Qs + n0 * HDIM);
        const float4* q1 = (const float4*)(Qs + n1 * HDIM);

        for (int j = 0; j < nm; j++) {
            const int m = lane + 32 * j;
            const float4* kr = (const float4*)(Ks + m * KSTR);
            float a0 = 0.f, a1 = 0.f;
            #pragma unroll
            for (int d4 = 0; d4 < 16; d4++) {
                float4 kvv = kr[d4];
                float4 qa = q0[d4];
                float4 qc = q1[d4];
                a0 = fmaf(kvv.x, qa.x, fmaf(kvv.y, qa.y,
                     fmaf(kvv.z, qa.z, fmaf(kvv.w, qa.w, a0))));
                a1 = fmaf(kvv.x, qc.x, fmaf(kvv.y, qc.y,
                     fmaf(kvv.z, qc.z, fmaf(kvv.w, qc.w, a1))));
            }
            a0 *= scale; a1 *= scale;

            float bias0 = (n0 == 0)
                ? ((m == 0) ? tb[191] : tb[192 + m - 1])
                : ((m == 0) ? tb[320 + n0 - 1] : tb[n0 - m + 127]);
            float bias1 = (n1 == 0)
                ? ((m == 0) ? tb[191] : tb[192 + m - 1])
                : ((m == 0) ? tb[320 + n1 - 1] : tb[n1 - m + 127]);
            a0 += bias0; a1 += bias1;

            bool m0 = false, m1 = false;
            if (use_l) { m0 = ml[n0 * MTOK + m] != 0; m1 = ml[n1 * MTOK + m] != 0; }
            if (use_r) { m0 = m0 || (mr[n0 * MTOK + m] != 0);
                         m1 = m1 || (mr[n1 * MTOK + m] != 0); }
            s0[j] = m0 ? NEG : a0;
            s1[j] = m1 ? NEG : a1;
        }

        float* Prow0 = Ps + warp * 2 * PSTR;
        float* Prow1 = Prow0 + PSTR;
        {
            float mx = s0[0];
            for (int j = 1; j < nm; j++) mx = fmaxf(mx, s0[j]);
            #pragma unroll
            for (int o = 16; o; o >>= 1) mx = fmaxf(mx, __shfl_xor_sync(~0u, mx, o));
            float sum = 0.f, p[5];
            for (int j = 0; j < nm; j++) { p[j] = __expf(s0[j] - mx); sum += p[j]; }
            #pragma unroll
            for (int o = 16; o; o >>= 1) sum += __shfl_xor_sync(~0u, sum, o);
            float inv = 1.f / sum;
            for (int j = 0; j < nm; j++) Prow0[lane + 32 * j] = p[j] * inv;
        }
        {
            float mx = s1[0];
            for (int j = 1; j < nm; j++) mx = fmaxf(mx, s1[j]);
            #pragma unroll
            for (int o = 16; o; o >>= 1) mx = fmaxf(mx, __shfl_xor_sync(~0u, mx, o));
            float sum = 0.f, p[5];
            for (int j = 0; j < nm; j++) { p[j] = __expf(s1[j] - mx); sum += p[j]; }
            #pragma unroll
            for (int o = 16; o; o >>= 1) sum += __shfl_xor_sync(~0u, sum, o);
            float inv = 1.f / sum;
            for (int j = 0; j < nm; j++) Prow1[lane + 32 * j] = p[j] * inv;
        }
        __syncwarp();

        float o00 = 0.f, o01 = 0.f, o10 = 0.f, o11 = 0.f;
        const float4* v0 = (const float4*)(Vt + lane * VSTR);
        const float4* v1 = (const float4*)(Vt + (lane + 32) * VSTR);
        const float4* p0 = (const float4*)Prow0;
        const float4* p1 = (const float4*)Prow1;
        #pragma unroll
        for (int m4 = 0; m4 < 32; m4++) {
            float4 va = v0[m4], vb = v1[m4];
            float4 pa = p0[m4], pb = p1[m4];
            o00 = fmaf(pa.x, va.x, fmaf(pa.y, va.y, fmaf(pa.z, va.z, fmaf(pa.w, va.w, o00))));
            o01 = fmaf(pa.x, vb.x, fmaf(pa.y, vb.y, fmaf(pa.z, vb.z, fmaf(pa.w, vb.w, o01))));
            o10 = fmaf(pb.x, va.x, fmaf(pb.y, va.y, fmaf(pb.z, va.z, fmaf(pb.w, va.w, o10))));
            o11 = fmaf(pb.x, vb.x, fmaf(pb.y, vb.y, fmaf(pb.z, vb.z, fmaf(pb.w, vb.w, o11))));
        }
        {
            float pt0 = Prow0[128], pt1 = Prow1[128];
            float va = Vt[lane * VSTR + 128], vb = Vt[(lane + 32) * VSTR + 128];
            o00 = fmaf(pt0, va, o00); o01 = fmaf(pt0, vb, o01);
            o10 = fmaf(pt1, va, o10); o11 = fmaf(pt1, vb, o11);
        }

        float* aor0 = ao + ((size_t)b * NTOK + n0) * CDIM + h * HDIM;
        aor0[lane]      = o00;
        aor0[lane + 32] = o01;
        if (two) {
            float* aor1 = ao + ((size_t)b * NTOK + n1) * CDIM + h * HDIM;
            aor1[lane]      = o10;
            aor1[lane + 32] = o11;
        }
        __syncwarp();
    }
}

// ---------------------------------------------------------------------------
extern "C" void kernel_launch(void* const* d_in, const int* in_sizes, int n_in,
                              void* d_out, int out_size)
{
    const float* x        = (const float*)d_in[0];
    const float* x_       = (const float*)d_in[1];
    const int*   mask_l   = (const int*)d_in[2];
    const int*   mask_r   = (const int*)d_in[3];
    const int*   nW_ptr   = (const int*)d_in[4];
    const float* Wq       = (const float*)d_in[5];
    const float* bq       = (const float*)d_in[6];
    const float* Wkv      = (const float*)d_in[7];
    const float* bkv      = (const float*)d_in[8];
    const float* Wp       = (const float*)d_in[9];
    const float* bp       = (const float*)d_in[10];
    const float* rel      = (const float*)d_in[11];
    const float* cls_self = (const float*)d_in[12];
    const float* cls_up   = (const float*)d_in[13];
    const float* cls_down = (const float*)d_in[14];

    const int BnW = in_sizes[0] / (NTOK * CDIM);   // 512
    const int Mq  = BnW * NTOK;                    // 33280
    const int Mkv = BnW * MTOK;                    // 66048

    float *qbuf, *kvbuf, *aobuf, *wqt, *wkvt, *wpt;
    cudaGetSymbolAddress((void**)&qbuf,  g_q);
    cudaGetSymbolAddress((void**)&kvbuf, g_kv);
    cudaGetSymbolAddress((void**)&aobuf, g_ao);
    cudaGetSymbolAddress((void**)&wqt,   g_wqt);
    cudaGetSymbolAddress((void**)&wkvt,  g_wkvt);
    cudaGetSymbolAddress((void**)&wpt,   g_wpt);

    // weights -> [N][perm(K)] tf32-rounded
    transpose_tf32_perm<<<dim3(CDIM / 32, CDIM / 32), 256>>>(Wq, wqt, CDIM, CDIM);
    transpose_tf32_perm<<<dim3(2 * CDIM / 32, CDIM / 32), 256>>>(Wkv, wkvt, CDIM, 2 * CDIM);
    transpose_tf32_perm<<<dim3(CDIM / 32, CDIM / 32), 256>>>(Wp, wpt, CDIM, CDIM);

    const int gsm = 2 * STAGE_W * sizeof(float);   // 81920
    cudaFuncSetAttribute(gemm_mma, cudaFuncAttributeMaxDynamicSharedMemorySize, gsm);

    gemm_mma<<<dim3(CDIM / 128, Mq / 128), 256, gsm>>>(x, wqt, bq, qbuf, Mq, CDIM, CDIM);
    gemm_mma<<<dim3(2 * CDIM / 128, Mkv / 128), 256, gsm>>>(x_, wkvt, bkv, kvbuf, Mkv, 2 * CDIM, CDIM);

    const int attn_smem = (MTOK * KSTR + HDIM * VSTR + NTOK * HDIM
                           + 8 * 2 * PSTR + 392) * sizeof(float);
    cudaFuncSetAttribute(attn_kernel, cudaFuncAttributeMaxDynamicSharedMemorySize, attn_smem);
    attn_kernel<<<dim3(NHEAD, BnW), 256, attn_smem>>>(
        qbuf, kvbuf, mask_l, mask_r, nW_ptr, rel, cls_self, cls_up, cls_down, aobuf);

    gemm_mma<<<dim3(CDIM / 128, Mq / 128), 256, gsm>>>(aobuf, wpt, bp, (float*)d_out, Mq, CDIM, CDIM);
}

// round 9
// speedup vs baseline: 1.4952x; 1.4952x over previous
#include <cuda_runtime.h>
#include <cuda_bf16.h>
#include <cstdint>

#define NTOK 65
#define MTOK 129
#define NHEAD 16
#define HDIM 64
#define CDIM 1024

// fp32 intermediates
__device__ float g_q [512 * NTOK * CDIM];
__device__ float g_kv[512 * MTOK * 2 * CDIM];
__device__ float g_ao[512 * NTOK * CDIM];     // tf32-rounded + k-permuted by attention
// tf32-rounded, k-permuted GEMM inputs
__device__ float g_xc  [512 * NTOK * CDIM];
__device__ float g_x_c [512 * MTOK * CDIM];
__device__ float g_wqt [CDIM * CDIM];         // [N][perm(K)]
__device__ float g_wkvt[2 * CDIM * CDIM];
__device__ float g_wpt [CDIM * CDIM];

__device__ __forceinline__ unsigned f2tf32(float x) {
    unsigned r;
    asm("cvt.rna.tf32.f32 %0, %1;" : "=r"(r) : "f"(x));
    return r;
}
__device__ __forceinline__ void cp16s(uint32_t s, const float* g) {
    asm volatile("cp.async.cg.shared.global [%0], [%1], 16;"
                 :: "r"(s), "l"(g) : "memory");
}
__device__ __forceinline__ uint32_t smem_u32(const void* p) {
    uint32_t a;
    asm("{ .reg .u64 t; cvta.to.shared.u64 t, %1; cvt.u32.u64 %0, t; }"
        : "=r"(a) : "l"(p));
    return a;
}
#define MMA_TF32(acc, a0, a1, a2, a3, b0, b1) \
    asm volatile( \
        "mma.sync.aligned.m16n8k8.row.col.f32.tf32.tf32.f32 " \
        "{%0,%1,%2,%3}, {%4,%5,%6,%7}, {%8,%9}, {%0,%1,%2,%3};" \
        : "+f"((acc)[0]), "+f"((acc)[1]), "+f"((acc)[2]), "+f"((acc)[3]) \
        : "r"(a0), "r"(a1), "r"(a2), "r"(a3), "r"(b0), "r"(b1))

// ---------------------------------------------------------------------------
// prepass: fp32 -> tf32-rounded, k-permuted (p(k)=(k&~7)|((k&3)<<1)|((k>>2)&1))
// ---------------------------------------------------------------------------
__global__ __launch_bounds__(256) void cvt_tf32_perm(
    const float4* __restrict__ in, float4* __restrict__ out, int n8)
{
    int i = blockIdx.x * blockDim.x + threadIdx.x;
    if (i < n8) {
        float4 a = in[2 * i], b = in[2 * i + 1];
        uint4 o0, o1;
        o0.x = f2tf32(a.x); o0.y = f2tf32(b.x);
        o0.z = f2tf32(a.y); o0.w = f2tf32(b.y);
        o1.x = f2tf32(a.z); o1.y = f2tf32(b.z);
        o1.z = f2tf32(a.w); o1.w = f2tf32(b.w);
        out[2 * i]     = *(float4*)&o0;
        out[2 * i + 1] = *(float4*)&o1;
    }
}

__global__ __launch_bounds__(256) void transpose_tf32_perm(
    const float* __restrict__ W, float* __restrict__ Wt, int K, int N)
{
    __shared__ float t[32][33];
    const int n0 = blockIdx.x * 32, k0 = blockIdx.y * 32;
    const int tx = threadIdx.x & 31, ty = threadIdx.x >> 5;
    #pragma unroll
    for (int i = 0; i < 4; i++)
        t[ty + 8 * i][tx] = W[(size_t)(k0 + ty + 8 * i) * N + n0 + tx];
    __syncthreads();
    const int pk = (tx & ~7) | ((tx & 3) << 1) | ((tx >> 2) & 1);
    #pragma unroll
    for (int i = 0; i < 4; i++)
        Wt[(size_t)(n0 + ty + 8 * i) * K + k0 + pk] =
            __uint_as_float(f2tf32(t[tx][ty + 8 * i]));
}

// ---------------------------------------------------------------------------
// R6 GEMM (frozen): 128x128x32 tile, 8 warps 64x32, cp.async 2-stage, 2 CTA/SM
// ---------------------------------------------------------------------------
#define GS 40
#define TILE_W (128 * GS)
#define STAGE_W (2 * TILE_W)

__global__ __launch_bounds__(256, 2) void gemm_mma(
    const float* __restrict__ A, const float* __restrict__ Bt,
    const float* __restrict__ bias, float* __restrict__ C,
    int M, int N, int K)
{
    extern __shared__ float smg[];

    const int tid  = threadIdx.x;
    const int lane = tid & 31;
    const int warp = tid >> 5;
    const int wm   = warp >> 2;
    const int wn   = warp & 3;
    const int g    = lane >> 2;
    const int t    = lane & 3;

    const int bn = blockIdx.x, bm = blockIdx.y;
    const float* Ag = A  + (size_t)bm * 128 * K;
    const float* Bg = Bt + (size_t)bn * 128 * K;
    const uint32_t sb = smem_u32(smg);

    float acc[4][4][4];
    #pragma unroll
    for (int i = 0; i < 4; i++)
        #pragma unroll
        for (int j = 0; j < 4; j++)
            #pragma unroll
            for (int r = 0; r < 4; r++) acc[i][j][r] = 0.f;

    auto issue = [&](int kt, int s) {
        const uint32_t base = sb + s * (STAGE_W * 4);
        #pragma unroll
        for (int it = 0; it < 8; it++) {
            int idx = tid + it * 256;
            int row = (idx >> 3) & 127, c = idx & 7;
            if (idx < 1024)
                cp16s(base + (row * GS + c * 4) * 4,
                      Ag + (size_t)row * K + kt + c * 4);
            else
                cp16s(base + (TILE_W + row * GS + c * 4) * 4,
                      Bg + (size_t)row * K + kt + c * 4);
        }
        asm volatile("cp.async.commit_group;" ::: "memory");
    };

    issue(0, 0);
    const int NT = K >> 5;
    for (int ti = 0; ti < NT; ti++) {
        const int cur = ti & 1;
        if (ti + 1 < NT) {
            issue((ti + 1) << 5, cur ^ 1);
            asm volatile("cp.async.wait_group 1;" ::: "memory");
        } else {
            asm volatile("cp.async.wait_group 0;" ::: "memory");
        }
        __syncthreads();

        const float* As = smg + cur * STAGE_W;
        const float* Bs = As + TILE_W;
        #pragma unroll
        for (int ks = 0; ks < 4; ks++) {
            const int k0 = ks * 8 + 2 * t;
            unsigned af[4][4];
            #pragma unroll
            for (int i = 0; i < 4; i++) {
                int r = wm * 64 + i * 16 + g;
                uint2 lo = *(const uint2*)(As + r * GS + k0);
                uint2 hi = *(const uint2*)(As + (r + 8) * GS + k0);
                af[i][0] = lo.x; af[i][2] = lo.y;
                af[i][1] = hi.x; af[i][3] = hi.y;
            }
            unsigned bf[4][2];
            #pragma unroll
            for (int j = 0; j < 4; j++) {
                int n = wn * 32 + j * 8 + g;
                uint2 bb = *(const uint2*)(Bs + n * GS + k0);
                bf[j][0] = bb.x; bf[j][1] = bb.y;
            }
            #pragma unroll
            for (int i = 0; i < 4; i++)
                #pragma unroll
                for (int j = 0; j < 4; j++)
                    MMA_TF32(acc[i][j], af[i][0], af[i][1], af[i][2], af[i][3],
                             bf[j][0], bf[j][1]);
        }
        __syncthreads();
    }

    #pragma unroll
    for (int i = 0; i < 4; i++) {
        int row0 = bm * 128 + wm * 64 + i * 16 + g;
        #pragma unroll
        for (int j = 0; j < 4; j++) {
            int col = bn * 128 + wn * 32 + j * 8 + t * 2;
            float b0 = bias[col], b1 = bias[col + 1];
            float2 v0 = make_float2(acc[i][j][0] + b0, acc[i][j][1] + b1);
            float2 v1 = make_float2(acc[i][j][2] + b0, acc[i][j][3] + b1);
            *(float2*)(C + (size_t)row0 * N + col)       = v0;
            *(float2*)(C + (size_t)(row0 + 8) * N + col) = v1;
        }
    }
}

// ---------------------------------------------------------------------------
// Tensor-core attention. One block per (head, window), 256 threads.
// Q[80pad x 64] A-op, K[136pad x 64] B-op -> S[80 x 136] in smem;
// SIMT softmax/bias/mask writes P (perm'd m) in place; V^T[64 x 136] B-op
// overlaid on dead Q/K; PV -> regs -> rounded+perm'd store to g_ao.
// ---------------------------------------------------------------------------
#define SSTR 136
#define QKS 72
#define OFF_Q (80 * SSTR)                 // 10880
#define OFF_K (OFF_Q + 80 * QKS)          // 16640
#define OFF_TB (OFF_K + 136 * QKS)        // 26432
#define ATTN_W (OFF_TB + 392)             // 26824 words

__global__ __launch_bounds__(256, 2) void attn_tc(
    const float* __restrict__ q, const float* __restrict__ kv,
    const int* __restrict__ mask_l,
    const int* __restrict__ mask_r,
    const int* __restrict__ nW_ptr,
    const float* __restrict__ rel_table,
    const float* __restrict__ cls_self,
    const float* __restrict__ cls_up,
    const float* __restrict__ cls_down,
    float* __restrict__ ao)
{
    const int h = blockIdx.x;
    const int b = blockIdx.y;
    const int tid = threadIdx.x;
    const int lane = tid & 31;
    const int warp = tid >> 5;
    const int g = lane >> 2;
    const int t = lane & 3;

    extern __shared__ float sm[];
    float* Ss = sm;
    float* Qs = sm + OFF_Q;
    float* Ks = sm + OFF_K;
    float* Vt = sm + OFF_Q;               // overlay (used after QK)
    float* tb = sm + OFF_TB;

    // bias tables
    for (int i = tid; i < 191; i += 256) tb[i] = rel_table[i * NHEAD + h];
    if (tid == 0) tb[191] = cls_self[h];
    for (int i = tid; i < 128; i += 256) tb[192 + i] = cls_up[h * (MTOK - 1) + i];
    for (int i = tid; i < 64; i += 256) tb[320 + i] = cls_down[h * (NTOK - 1) + i];

    // zero K pad rows 129..135
    for (int i = tid; i < 7 * QKS; i += 256) Ks[129 * QKS + i] = 0.f;

    // stage Q (65 rows x 8 k-groups), rounded + permuted
    const float* qb = q + (size_t)b * NTOK * CDIM + h * HDIM;
    for (int idx = tid; idx < 65 * 8; idx += 256) {
        int r = idx >> 3, gp = idx & 7;
        const float* p = qb + (size_t)r * CDIM + gp * 8;
        float4 a = *(const float4*)p, c = *(const float4*)(p + 4);
        uint4 w0, w1;
        w0.x = f2tf32(a.x); w0.y = f2tf32(c.x); w0.z = f2tf32(a.y); w0.w = f2tf32(c.y);
        w1.x = f2tf32(a.z); w1.y = f2tf32(c.z); w1.z = f2tf32(a.w); w1.w = f2tf32(c.w);
        *(uint4*)(Qs + r * QKS + gp * 8)     = w0;
        *(uint4*)(Qs + r * QKS + gp * 8 + 4) = w1;
    }
    // stage K (129 rows)
    const float* kb = kv + (size_t)b * MTOK * 2 * CDIM + h * HDIM;
    for (int idx = tid; idx < 129 * 8; idx += 256) {
        int r = idx >> 3, gp = idx & 7;
        const float* p = kb + (size_t)r * 2048 + gp * 8;
        float4 a = *(const float4*)p, c = *(const float4*)(p + 4);
        uint4 w0, w1;
        w0.x = f2tf32(a.x); w0.y = f2tf32(c.x); w0.z = f2tf32(a.y); w0.w = f2tf32(c.y);
        w1.x = f2tf32(a.z); w1.y = f2tf32(c.z); w1.z = f2tf32(a.w); w1.w = f2tf32(c.w);
        *(uint4*)(Ks + r * QKS + gp * 8)     = w0;
        *(uint4*)(Ks + r * QKS + gp * 8 + 4) = w1;
    }
    __syncthreads();

    // ---- QK^T: warp owns n-tiles {warp, warp+8, (warp==0: 16)} ----
    {
        int ntv[3]; int nc = 0;
        for (int nt = warp; nt < 17; nt += 8) ntv[nc++] = nt;
        float acc[5][3][4];
        #pragma unroll
        for (int i = 0; i < 5; i++)
            #pragma unroll
            for (int c = 0; c < 3; c++)
                #pragma unroll
                for (int r = 0; r < 4; r++) acc[i][c][r] = 0.f;

        #pragma unroll
        for (int ks = 0; ks < 8; ks++) {
            const int k0 = ks * 8 + 2 * t;
            unsigned af[5][4];
            #pragma unroll
            for (int i = 0; i < 5; i++) {
                int r = i * 16 + g;
                uint2 lo = *(const uint2*)(Qs + r * QKS + k0);
                uint2 hi = *(const uint2*)(Qs + (r + 8) * QKS + k0);
                af[i][0] = lo.x; af[i][2] = lo.y;
                af[i][1] = hi.x; af[i][3] = hi.y;
            }
            for (int c = 0; c < nc; c++) {
                int n = ntv[c] * 8 + g;
                uint2 bb = *(const uint2*)(Ks + n * QKS + k0);
                #pragma unroll
                for (int i = 0; i < 5; i++)
                    MMA_TF32(acc[i][c], af[i][0], af[i][1], af[i][2], af[i][3],
                             bb.x, bb.y);
            }
        }
        // write S
        for (int c = 0; c < nc; c++) {
            int col = ntv[c] * 8 + 2 * t;
            #pragma unroll
            for (int i = 0; i < 5; i++) {
                int q0 = i * 16 + g;
                *(float2*)(Ss + q0 * SSTR + col) =
                    make_float2(acc[i][c][0], acc[i][c][1]);
                *(float2*)(Ss + (q0 + 8) * SSTR + col) =
                    make_float2(acc[i][c][2], acc[i][c][3]);
            }
        }
    }
    __syncthreads();

    // ---- stage V^T into overlay (rounded, m permuted), zero pad cols ----
    const float* vb = kb + CDIM;
    for (int idx = tid; idx < 129 * 16; idx += 256) {
        int m = idx >> 4, d4 = (idx & 15) << 2;
        int pm = (m & ~7) | ((m & 3) << 1) | ((m >> 2) & 1);
        float4 v = *(const float4*)(vb + (size_t)m * 2048 + d4);
        Vt[(d4 + 0) * SSTR + pm] = __uint_as_float(f2tf32(v.x));
        Vt[(d4 + 1) * SSTR + pm] = __uint_as_float(f2tf32(v.y));
        Vt[(d4 + 2) * SSTR + pm] = __uint_as_float(f2tf32(v.z));
        Vt[(d4 + 3) * SSTR + pm] = __uint_as_float(f2tf32(v.w));
    }
    for (int idx = tid; idx < 64 * 7; idx += 256) {
        int n = idx / 7, c = 129 + idx % 7;
        Vt[n * SSTR + c] = 0.f;
    }

    // ---- softmax + bias + mask (SIMT, in place; P written at perm(m)) ----
    {
        const int nW = *nW_ptr;
        const int mc = (nW < 2) ? nW : 2;
        const int w = b % nW;
        const bool use_l = (w < mc);
        const bool use_r = (w >= nW - mc);
        const int* ml = mask_l + (size_t)w * NTOK * MTOK;
        const int* mr = mask_r + (size_t)(2 - mc + (w - (nW - mc))) * NTOK * MTOK;
        const float scale = 0.125f;
        const float NEG = -3.402823466e38f;

        for (int qr = warp; qr < NTOK; qr += 8) {
            const int nm = (lane == 0) ? 5 : 4;
            float s[5];
            for (int j = 0; j < nm; j++) {
                const int m = lane + 32 * j;
                float a = Ss[qr * SSTR + m] * scale;
                float bias = (qr == 0)
                    ? ((m == 0) ? tb[191] : tb[192 + m - 1])
                    : ((m == 0) ? tb[320 + qr - 1] : tb[qr - m + 127]);
                a += bias;
                bool msk = false;
                if (use_l) msk = ml[qr * MTOK + m] != 0;
                if (use_r) msk = msk || (mr[qr * MTOK + m] != 0);
                s[j] = msk ? NEG : a;
            }
            float mx = s[0];
            for (int j = 1; j < nm; j++) mx = fmaxf(mx, s[j]);
            #pragma unroll
            for (int o = 16; o; o >>= 1) mx = fmaxf(mx, __shfl_xor_sync(~0u, mx, o));
            float sum = 0.f, p[5];
            for (int j = 0; j < nm; j++) { p[j] = __expf(s[j] - mx); sum += p[j]; }
            #pragma unroll
            for (int o = 16; o; o >>= 1) sum += __shfl_xor_sync(~0u, sum, o);
            const float inv = 1.f / sum;
            __syncwarp();
            for (int j = 0; j < nm; j++) {
                const int m = lane + 32 * j;
                const int pm = (m & ~7) | ((m & 3) << 1) | ((m >> 2) & 1);
                Ss[qr * SSTR + pm] = p[j] * inv;
            }
        }
    }
    __syncthreads();

    // ---- PV: warp owns d-tile `warp` (8 cols), k over 136 ----
    {
        float acc[5][4];
        #pragma unroll
        for (int i = 0; i < 5; i++)
            #pragma unroll
            for (int r = 0; r < 4; r++) acc[i][r] = 0.f;

        for (int ks = 0; ks < 17; ks++) {
            const int k0 = ks * 8 + 2 * t;
            const int n = warp * 8 + g;
            uint2 bb = *(const uint2*)(Vt + n * SSTR + k0);
            #pragma unroll
            for (int i = 0; i < 5; i++) {
                int r = i * 16 + g;
                uint2 lo = *(const uint2*)(Ss + r * SSTR + k0);
                uint2 hi = *(const uint2*)(Ss + (r + 8) * SSTR + k0);
                MMA_TF32(acc[i], lo.x, hi.x, lo.y, hi.y, bb.x, bb.y);
            }
        }
        // output: rounded + k-permuted for the downstream GEMM
        const int c0 = 2 * t, c1 = 2 * t + 1;
        const int p0 = ((c0 & 3) << 1) | ((c0 >> 2) & 1);
        const int p1 = ((c1 & 3) << 1) | ((c1 >> 2) & 1);
        const int colbase = h * HDIM + warp * 8;
        #pragma unroll
        for (int i = 0; i < 5; i++) {
            int q0 = i * 16 + g, q1 = q0 + 8;
            if (q0 < NTOK) {
                float* dst = ao + ((size_t)b * NTOK + q0) * CDIM + colbase;
                dst[p0] = __uint_as_float(f2tf32(acc[i][0]));
                dst[p1] = __uint_as_float(f2tf32(acc[i][1]));
            }
            if (q1 < NTOK) {
                float* dst = ao + ((size_t)b * NTOK + q1) * CDIM + colbase;
                dst[p0] = __uint_as_float(f2tf32(acc[i][2]));
                dst[p1] = __uint_as_float(f2tf32(acc[i][3]));
            }
        }
    }
}

// ---------------------------------------------------------------------------
extern "C" void kernel_launch(void* const* d_in, const int* in_sizes, int n_in,
                              void* d_out, int out_size)
{
    const float* x        = (const float*)d_in[0];
    const float* x_       = (const float*)d_in[1];
    const int*   mask_l   = (const int*)d_in[2];
    const int*   mask_r   = (const int*)d_in[3];
    const int*   nW_ptr   = (const int*)d_in[4];
    const float* Wq       = (const float*)d_in[5];
    const float* bq       = (const float*)d_in[6];
    const float* Wkv      = (const float*)d_in[7];
    const float* bkv      = (const float*)d_in[8];
    const float* Wp       = (const float*)d_in[9];
    const float* bp       = (const float*)d_in[10];
    const float* rel      = (const float*)d_in[11];
    const float* cls_self = (const float*)d_in[12];
    const float* cls_up   = (const float*)d_in[13];
    const float* cls_down = (const float*)d_in[14];

    const int BnW = in_sizes[0] / (NTOK * CDIM);   // 512
    const int Mq  = BnW * NTOK;                    // 33280
    const int Mkv = BnW * MTOK;                    // 66048

    float *qbuf, *kvbuf, *aobuf, *xc, *x_c, *wqt, *wkvt, *wpt;
    cudaGetSymbolAddress((void**)&qbuf,  g_q);
    cudaGetSymbolAddress((void**)&kvbuf, g_kv);
    cudaGetSymbolAddress((void**)&aobuf, g_ao);
    cudaGetSymbolAddress((void**)&xc,    g_xc);
    cudaGetSymbolAddress((void**)&x_c,   g_x_c);
    cudaGetSymbolAddress((void**)&wqt,   g_wqt);
    cudaGetSymbolAddress((void**)&wkvt,  g_wkvt);
    cudaGetSymbolAddress((void**)&wpt,   g_wpt);

    auto cvt = [&](const float* src, float* dst, long long n) {
        int n8 = (int)(n / 8);
        cvt_tf32_perm<<<(n8 + 255) / 256, 256>>>((const float4*)src, (float4*)dst, n8);
    };
    cvt(x,  xc,  (long long)Mq * CDIM);
    cvt(x_, x_c, (long long)Mkv * CDIM);
    transpose_tf32_perm<<<dim3(CDIM / 32, CDIM / 32), 256>>>(Wq, wqt, CDIM, CDIM);
    transpose_tf32_perm<<<dim3(2 * CDIM / 32, CDIM / 32), 256>>>(Wkv, wkvt, CDIM, 2 * CDIM);
    transpose_tf32_perm<<<dim3(CDIM / 32, CDIM / 32), 256>>>(Wp, wpt, CDIM, CDIM);

    const int gsm = 2 * STAGE_W * sizeof(float);   // 81920
    cudaFuncSetAttribute(gemm_mma, cudaFuncAttributeMaxDynamicSharedMemorySize, gsm);

    gemm_mma<<<dim3(CDIM / 128, Mq / 128), 256, gsm>>>(xc, wqt, bq, qbuf, Mq, CDIM, CDIM);
    gemm_mma<<<dim3(2 * CDIM / 128, Mkv / 128), 256, gsm>>>(x_c, wkvt, bkv, kvbuf, Mkv, 2 * CDIM, CDIM);

    const int asm_bytes = ATTN_W * sizeof(float);  // 107296
    cudaFuncSetAttribute(attn_tc, cudaFuncAttributeMaxDynamicSharedMemorySize, asm_bytes);
    attn_tc<<<dim3(NHEAD, BnW), 256, asm_bytes>>>(
        qbuf, kvbuf, mask_l, mask_r, nW_ptr, rel, cls_self, cls_up, cls_down, aobuf);

    gemm_mma<<<dim3(CDIM / 128, Mq / 128), 256, gsm>>>(aobuf, wpt, bp, (float*)d_out, Mq, CDIM, CDIM);
}

// round 10
// speedup vs baseline: 1.5438x; 1.0325x over previous
#include <cuda_runtime.h>
#include <cuda_bf16.h>
#include <cstdint>

#define NTOK 65
#define MTOK 129
#define NHEAD 16
#define HDIM 64
#define CDIM 1024

// fp32 intermediates
__device__ float g_q [512 * NTOK * CDIM];
__device__ float g_kv[512 * MTOK * 2 * CDIM];
__device__ float g_ao[512 * NTOK * CDIM];     // tf32-rounded + k-permuted by attention
// tf32-rounded, k-permuted GEMM inputs
__device__ float g_xc  [512 * NTOK * CDIM];
__device__ float g_x_c [512 * MTOK * CDIM];
__device__ float g_wqt [CDIM * CDIM];         // [N][perm(K)]
__device__ float g_wkvt[2 * CDIM * CDIM];
__device__ float g_wpt [CDIM * CDIM];

__device__ __forceinline__ unsigned f2tf32(float x) {
    unsigned r;
    asm("cvt.rna.tf32.f32 %0, %1;" : "=r"(r) : "f"(x));
    return r;
}
__device__ __forceinline__ void cp16s(uint32_t s, const float* g) {
    asm volatile("cp.async.cg.shared.global [%0], [%1], 16;"
                 :: "r"(s), "l"(g) : "memory");
}
__device__ __forceinline__ uint32_t smem_u32(const void* p) {
    uint32_t a;
    asm("{ .reg .u64 t; cvta.to.shared.u64 t, %1; cvt.u32.u64 %0, t; }"
        : "=r"(a) : "l"(p));
    return a;
}
#define MMA_TF32(acc, a0, a1, a2, a3, b0, b1) \
    asm volatile( \
        "mma.sync.aligned.m16n8k8.row.col.f32.tf32.tf32.f32 " \
        "{%0,%1,%2,%3}, {%4,%5,%6,%7}, {%8,%9}, {%0,%1,%2,%3};" \
        : "+f"((acc)[0]), "+f"((acc)[1]), "+f"((acc)[2]), "+f"((acc)[3]) \
        : "r"(a0), "r"(a1), "r"(a2), "r"(a3), "r"(b0), "r"(b1))

// ---------------------------------------------------------------------------
// prepass: fp32 -> tf32-rounded, k-permuted (p(k)=(k&~7)|((k&3)<<1)|((k>>2)&1))
// ---------------------------------------------------------------------------
__global__ __launch_bounds__(256) void cvt_tf32_perm(
    const float4* __restrict__ in, float4* __restrict__ out, int n8)
{
    int i = blockIdx.x * blockDim.x + threadIdx.x;
    if (i < n8) {
        float4 a = in[2 * i], b = in[2 * i + 1];
        uint4 o0, o1;
        o0.x = f2tf32(a.x); o0.y = f2tf32(b.x);
        o0.z = f2tf32(a.y); o0.w = f2tf32(b.y);
        o1.x = f2tf32(a.z); o1.y = f2tf32(b.z);
        o1.z = f2tf32(a.w); o1.w = f2tf32(b.w);
        out[2 * i]     = *(float4*)&o0;
        out[2 * i + 1] = *(float4*)&o1;
    }
}

__global__ __launch_bounds__(256) void transpose_tf32_perm(
    const float* __restrict__ W, float* __restrict__ Wt, int K, int N)
{
    __shared__ float t[32][33];
    const int n0 = blockIdx.x * 32, k0 = blockIdx.y * 32;
    const int tx = threadIdx.x & 31, ty = threadIdx.x >> 5;
    #pragma unroll
    for (int i = 0; i < 4; i++)
        t[ty + 8 * i][tx] = W[(size_t)(k0 + ty + 8 * i) * N + n0 + tx];
    __syncthreads();
    const int pk = (tx & ~7) | ((tx & 3) << 1) | ((tx >> 2) & 1);
    #pragma unroll
    for (int i = 0; i < 4; i++)
        Wt[(size_t)(n0 + ty + 8 * i) * K + k0 + pk] =
            __uint_as_float(f2tf32(t[tx][ty + 8 * i]));
}

// ---------------------------------------------------------------------------
// R6 GEMM (frozen): 128x128x32 tile, 8 warps 64x32, cp.async 2-stage, 2 CTA/SM
// ---------------------------------------------------------------------------
#define GS 40
#define TILE_W (128 * GS)
#define STAGE_W (2 * TILE_W)

__global__ __launch_bounds__(256, 2) void gemm_mma(
    const float* __restrict__ A, const float* __restrict__ Bt,
    const float* __restrict__ bias, float* __restrict__ C,
    int M, int N, int K)
{
    extern __shared__ float smg[];

    const int tid  = threadIdx.x;
    const int lane = tid & 31;
    const int warp = tid >> 5;
    const int wm   = warp >> 2;
    const int wn   = warp & 3;
    const int g    = lane >> 2;
    const int t    = lane & 3;

    const int bn = blockIdx.x, bm = blockIdx.y;
    const float* Ag = A  + (size_t)bm * 128 * K;
    const float* Bg = Bt + (size_t)bn * 128 * K;
    const uint32_t sb = smem_u32(smg);

    float acc[4][4][4];
    #pragma unroll
    for (int i = 0; i < 4; i++)
        #pragma unroll
        for (int j = 0; j < 4; j++)
            #pragma unroll
            for (int r = 0; r < 4; r++) acc[i][j][r] = 0.f;

    auto issue = [&](int kt, int s) {
        const uint32_t base = sb + s * (STAGE_W * 4);
        #pragma unroll
        for (int it = 0; it < 8; it++) {
            int idx = tid + it * 256;
            int row = (idx >> 3) & 127, c = idx & 7;
            if (idx < 1024)
                cp16s(base + (row * GS + c * 4) * 4,
                      Ag + (size_t)row * K + kt + c * 4);
            else
                cp16s(base + (TILE_W + row * GS + c * 4) * 4,
                      Bg + (size_t)row * K + kt + c * 4);
        }
        asm volatile("cp.async.commit_group;" ::: "memory");
    };

    issue(0, 0);
    const int NT = K >> 5;
    for (int ti = 0; ti < NT; ti++) {
        const int cur = ti & 1;
        if (ti + 1 < NT) {
            issue((ti + 1) << 5, cur ^ 1);
            asm volatile("cp.async.wait_group 1;" ::: "memory");
        } else {
            asm volatile("cp.async.wait_group 0;" ::: "memory");
        }
        __syncthreads();

        const float* As = smg + cur * STAGE_W;
        const float* Bs = As + TILE_W;
        #pragma unroll
        for (int ks = 0; ks < 4; ks++) {
            const int k0 = ks * 8 + 2 * t;
            unsigned af[4][4];
            #pragma unroll
            for (int i = 0; i < 4; i++) {
                int r = wm * 64 + i * 16 + g;
                uint2 lo = *(const uint2*)(As + r * GS + k0);
                uint2 hi = *(const uint2*)(As + (r + 8) * GS + k0);
                af[i][0] = lo.x; af[i][2] = lo.y;
                af[i][1] = hi.x; af[i][3] = hi.y;
            }
            unsigned bf[4][2];
            #pragma unroll
            for (int j = 0; j < 4; j++) {
                int n = wn * 32 + j * 8 + g;
                uint2 bb = *(const uint2*)(Bs + n * GS + k0);
                bf[j][0] = bb.x; bf[j][1] = bb.y;
            }
            #pragma unroll
            for (int i = 0; i < 4; i++)
                #pragma unroll
                for (int j = 0; j < 4; j++)
                    MMA_TF32(acc[i][j], af[i][0], af[i][1], af[i][2], af[i][3],
                             bf[j][0], bf[j][1]);
        }
        __syncthreads();
    }

    #pragma unroll
    for (int i = 0; i < 4; i++) {
        int row0 = bm * 128 + wm * 64 + i * 16 + g;
        #pragma unroll
        for (int j = 0; j < 4; j++) {
            int col = bn * 128 + wn * 32 + j * 8 + t * 2;
            float b0 = bias[col], b1 = bias[col + 1];
            float2 v0 = make_float2(acc[i][j][0] + b0, acc[i][j][1] + b1);
            float2 v1 = make_float2(acc[i][j][2] + b0, acc[i][j][3] + b1);
            *(float2*)(C + (size_t)row0 * N + col)       = v0;
            *(float2*)(C + (size_t)(row0 + 8) * N + col) = v1;
        }
    }
}

// ---------------------------------------------------------------------------
// Tensor-core attention v2. One block per (head, window), 256 threads.
// QK^T via mma (16 n-tiles, 2/warp; col 128 via SIMT dot); softmax SIMT
// in place (P written k-permuted, pad cols zeroed); PV via mma with V
// B-fragments loaded DIRECTLY from gmem (V is read exactly once) with
// in-register cvt.rna and prefetch depth 2.
// ---------------------------------------------------------------------------
#define SSTR 136
#define QKS 72
#define OFF_Q (80 * SSTR)                 // 10880
#define OFF_K (OFF_Q + 80 * QKS)          // 16640
#define OFF_TB (OFF_K + 129 * QKS)        // 25928
#define ATTN_W (OFF_TB + 392)             // 26320 words = 105280 B

__global__ __launch_bounds__(256, 2) void attn_tc(
    const float* __restrict__ q, const float* __restrict__ kv,
    const int* __restrict__ mask_l,
    const int* __restrict__ mask_r,
    const int* __restrict__ nW_ptr,
    const float* __restrict__ rel_table,
    const float* __restrict__ cls_self,
    const float* __restrict__ cls_up,
    const float* __restrict__ cls_down,
    float* __restrict__ ao)
{
    const int h = blockIdx.x;
    const int b = blockIdx.y;
    const int tid = threadIdx.x;
    const int lane = tid & 31;
    const int warp = tid >> 5;
    const int g = lane >> 2;
    const int t = lane & 3;

    extern __shared__ float sm[];
    float* Ss = sm;                       // [80][136] scores -> P
    float* Qs = sm + OFF_Q;               // [80][72] (65 real rows)
    float* Ks = sm + OFF_K;               // [129][72]
    float* tb = sm + OFF_TB;

    // bias tables
    for (int i = tid; i < 191; i += 256) tb[i] = rel_table[i * NHEAD + h];
    if (tid == 0) tb[191] = cls_self[h];
    for (int i = tid; i < 128; i += 256) tb[192 + i] = cls_up[h * (MTOK - 1) + i];
    for (int i = tid; i < 64; i += 256) tb[320 + i] = cls_down[h * (NTOK - 1) + i];

    // stage Q (65 rows x 8 k-groups), rounded + permuted
    const float* qb = q + (size_t)b * NTOK * CDIM + h * HDIM;
    for (int idx = tid; idx < 65 * 8; idx += 256) {
        int r = idx >> 3, gp = idx & 7;
        const float* p = qb + (size_t)r * CDIM + gp * 8;
        float4 a = *(const float4*)p, c = *(const float4*)(p + 4);
        uint4 w0, w1;
        w0.x = f2tf32(a.x); w0.y = f2tf32(c.x); w0.z = f2tf32(a.y); w0.w = f2tf32(c.y);
        w1.x = f2tf32(a.z); w1.y = f2tf32(c.z); w1.z = f2tf32(a.w); w1.w = f2tf32(c.w);
        *(uint4*)(Qs + r * QKS + gp * 8)     = w0;
        *(uint4*)(Qs + r * QKS + gp * 8 + 4) = w1;
    }
    // stage K (129 rows)
    const float* kb = kv + (size_t)b * MTOK * 2 * CDIM + h * HDIM;
    for (int idx = tid; idx < 129 * 8; idx += 256) {
        int r = idx >> 3, gp = idx & 7;
        const float* p = kb + (size_t)r * 2048 + gp * 8;
        float4 a = *(const float4*)p, c = *(const float4*)(p + 4);
        uint4 w0, w1;
        w0.x = f2tf32(a.x); w0.y = f2tf32(c.x); w0.z = f2tf32(a.y); w0.w = f2tf32(c.y);
        w1.x = f2tf32(a.z); w1.y = f2tf32(c.z); w1.z = f2tf32(a.w); w1.w = f2tf32(c.w);
        *(uint4*)(Ks + r * QKS + gp * 8)     = w0;
        *(uint4*)(Ks + r * QKS + gp * 8 + 4) = w1;
    }
    __syncthreads();

    // ---- QK^T mma: warp owns n-tiles {warp, warp+8} (cols 0..127) ----
    {
        float acc[5][2][4];
        #pragma unroll
        for (int i = 0; i < 5; i++)
            #pragma unroll
            for (int c = 0; c < 2; c++)
                #pragma unroll
                for (int r = 0; r < 4; r++) acc[i][c][r] = 0.f;

        #pragma unroll
        for (int ks = 0; ks < 8; ks++) {
            const int k0 = ks * 8 + 2 * t;
            unsigned af[5][4];
            #pragma unroll
            for (int i = 0; i < 5; i++) {
                int r = i * 16 + g;
                uint2 lo = *(const uint2*)(Qs + r * QKS + k0);
                uint2 hi = *(const uint2*)(Qs + (r + 8) * QKS + k0);
                af[i][0] = lo.x; af[i][2] = lo.y;
                af[i][1] = hi.x; af[i][3] = hi.y;
            }
            #pragma unroll
            for (int c = 0; c < 2; c++) {
                int n = (warp + 8 * c) * 8 + g;
                uint2 bb = *(const uint2*)(Ks + n * QKS + k0);
                #pragma unroll
                for (int i = 0; i < 5; i++)
                    MMA_TF32(acc[i][c], af[i][0], af[i][1], af[i][2], af[i][3],
                             bb.x, bb.y);
            }
        }
        #pragma unroll
        for (int c = 0; c < 2; c++) {
            int col = (warp + 8 * c) * 8 + 2 * t;
            #pragma unroll
            for (int i = 0; i < 5; i++) {
                int q0 = i * 16 + g;
                *(float2*)(Ss + q0 * SSTR + col) =
                    make_float2(acc[i][c][0], acc[i][c][1]);
                *(float2*)(Ss + (q0 + 8) * SSTR + col) =
                    make_float2(acc[i][c][2], acc[i][c][3]);
            }
        }
        // col 128 via SIMT dot (K row 128 hoisted)
        const float k0v = Ks[128 * QKS + lane];
        const float k1v = Ks[128 * QKS + 32 + lane];
        for (int qr = warp; qr < NTOK; qr += 8) {
            float s = fmaf(Qs[qr * QKS + lane], k0v,
                           Qs[qr * QKS + 32 + lane] * k1v);
            #pragma unroll
            for (int o = 16; o; o >>= 1) s += __shfl_xor_sync(~0u, s, o);
            if (lane == 0) Ss[qr * SSTR + 128] = s;
        }
    }
    __syncthreads();

    // ---- softmax + bias + mask (in place; P written at perm(m)) ----
    {
        const int nW = *nW_ptr;
        const int mc = (nW < 2) ? nW : 2;
        const int w = b % nW;
        const bool use_l = (w < mc);
        const bool use_r = (w >= nW - mc);
        const int* ml = mask_l + (size_t)w * NTOK * MTOK;
        const int* mr = mask_r + (size_t)(2 - mc + (w - (nW - mc))) * NTOK * MTOK;
        const float scale = 0.125f;
        const float NEG = -3.402823466e38f;

        for (int qr = warp; qr < NTOK; qr += 8) {
            const int nm = (lane == 0) ? 5 : 4;
            float s[5];
            for (int j = 0; j < nm; j++) {
                const int m = lane + 32 * j;
                float a = Ss[qr * SSTR + m] * scale;
                float bias = (qr == 0)
                    ? ((m == 0) ? tb[191] : tb[192 + m - 1])
                    : ((m == 0) ? tb[320 + qr - 1] : tb[qr - m + 127]);
                a += bias;
                bool msk = false;
                if (use_l) msk = ml[qr * MTOK + m] != 0;
                if (use_r) msk = msk || (mr[qr * MTOK + m] != 0);
                s[j] = msk ? NEG : a;
            }
            float mx = s[0];
            for (int j = 1; j < nm; j++) mx = fmaxf(mx, s[j]);
            #pragma unroll
            for (int o = 16; o; o >>= 1) mx = fmaxf(mx, __shfl_xor_sync(~0u, mx, o));
            float sum = 0.f, p[5];
            for (int j = 0; j < nm; j++) { p[j] = __expf(s[j] - mx); sum += p[j]; }
            #pragma unroll
            for (int o = 16; o; o >>= 1) sum += __shfl_xor_sync(~0u, sum, o);
            const float inv = 1.f / sum;
            __syncwarp();
            for (int j = 0; j < nm; j++) {
                const int m = lane + 32 * j;
                const int pm = (m & ~7) | ((m & 3) << 1) | ((m >> 2) & 1);
                Ss[qr * SSTR + pm] = p[j] * inv;
            }
            if (lane < 7) Ss[qr * SSTR + 129 + lane] = 0.f;   // NaN-safe pad
        }
    }
    __syncthreads();

    // ---- PV mma: warp owns d-cols warp*8..+7; V direct from gmem ----
    {
        const float* vcol = kb + CDIM + warp * 8 + g;   // V[m][d], stride 2048
        float acc[5][4];
        #pragma unroll
        for (int i = 0; i < 5; i++)
            #pragma unroll
            for (int r = 0; r < 4; r++) acc[i][r] = 0.f;

        // prefetch ring (depth 2): logical m = ks*8+t and ks*8+t+4
        float pva[2], pvb[2];
        pva[0] = vcol[(size_t)(t) * 2048];
        pvb[0] = vcol[(size_t)(t + 4) * 2048];
        pva[1] = vcol[(size_t)(8 + t) * 2048];
        pvb[1] = vcol[(size_t)(12 + t) * 2048];

        #pragma unroll
        for (int ks = 0; ks < 17; ks++) {
            const int cur = ks & 1;
            const unsigned b0 = f2tf32(pva[cur]);
            const unsigned b1 = f2tf32(pvb[cur]);
            if (ks + 2 <= 16) {
                const int m0 = (ks + 2) * 8 + t, m1 = m0 + 4;
                pva[cur] = (m0 < MTOK) ? vcol[(size_t)m0 * 2048] : 0.f;
                pvb[cur] = (m1 < MTOK) ? vcol[(size_t)m1 * 2048] : 0.f;
            }
            const int k0 = ks * 8 + 2 * t;
            #pragma unroll
            for (int i = 0; i < 5; i++) {
                int r = i * 16 + g;
                uint2 lo = *(const uint2*)(Ss + r * SSTR + k0);
                uint2 hi = *(const uint2*)(Ss + (r + 8) * SSTR + k0);
                MMA_TF32(acc[i], lo.x, hi.x, lo.y, hi.y, b0, b1);
            }
        }
        // output: rounded + k-permuted for the downstream GEMM
        const int c0 = 2 * t, c1 = 2 * t + 1;
        const int p0 = ((c0 & 3) << 1) | ((c0 >> 2) & 1);
        const int p1 = ((c1 & 3) << 1) | ((c1 >> 2) & 1);
        const int colbase = h * HDIM + warp * 8;
        #pragma unroll
        for (int i = 0; i < 5; i++) {
            int q0 = i * 16 + g, q1 = q0 + 8;
            if (q0 < NTOK) {
                float* dst = ao + ((size_t)b * NTOK + q0) * CDIM + colbase;
                dst[p0] = __uint_as_float(f2tf32(acc[i][0]));
                dst[p1] = __uint_as_float(f2tf32(acc[i][1]));
            }
            if (q1 < NTOK) {
                float* dst = ao + ((size_t)b * NTOK + q1) * CDIM + colbase;
                dst[p0] = __uint_as_float(f2tf32(acc[i][2]));
                dst[p1] = __uint_as_float(f2tf32(acc[i][3]));
            }
        }
    }
}

// ---------------------------------------------------------------------------
extern "C" void kernel_launch(void* const* d_in, const int* in_sizes, int n_in,
                              void* d_out, int out_size)
{
    const float* x        = (const float*)d_in[0];
    const float* x_       = (const float*)d_in[1];
    const int*   mask_l   = (const int*)d_in[2];
    const int*   mask_r   = (const int*)d_in[3];
    const int*   nW_ptr   = (const int*)d_in[4];
    const float* Wq       = (const float*)d_in[5];
    const float* bq       = (const float*)d_in[6];
    const float* Wkv      = (const float*)d_in[7];
    const float* bkv      = (const float*)d_in[8];
    const float* Wp       = (const float*)d_in[9];
    const float* bp       = (const float*)d_in[10];
    const float* rel      = (const float*)d_in[11];
    const float* cls_self = (const float*)d_in[12];
    const float* cls_up   = (const float*)d_in[13];
    const float* cls_down = (const float*)d_in[14];

    const int BnW = in_sizes[0] / (NTOK * CDIM);   // 512
    const int Mq  = BnW * NTOK;                    // 33280
    const int Mkv = BnW * MTOK;                    // 66048

    float *qbuf, *kvbuf, *aobuf, *xc, *x_c, *wqt, *wkvt, *wpt;
    cudaGetSymbolAddress((void**)&qbuf,  g_q);
    cudaGetSymbolAddress((void**)&kvbuf, g_kv);
    cudaGetSymbolAddress((void**)&aobuf, g_ao);
    cudaGetSymbolAddress((void**)&xc,    g_xc);
    cudaGetSymbolAddress((void**)&x_c,   g_x_c);
    cudaGetSymbolAddress((void**)&wqt,   g_wqt);
    cudaGetSymbolAddress((void**)&wkvt,  g_wkvt);
    cudaGetSymbolAddress((void**)&wpt,   g_wpt);

    auto cvt = [&](const float* src, float* dst, long long n) {
        int n8 = (int)(n / 8);
        cvt_tf32_perm<<<(n8 + 255) / 256, 256>>>((const float4*)src, (float4*)dst, n8);
    };
    cvt(x,  xc,  (long long)Mq * CDIM);
    cvt(x_, x_c, (long long)Mkv * CDIM);
    transpose_tf32_perm<<<dim3(CDIM / 32, CDIM / 32), 256>>>(Wq, wqt, CDIM, CDIM);
    transpose_tf32_perm<<<dim3(2 * CDIM / 32, CDIM / 32), 256>>>(Wkv, wkvt, CDIM, 2 * CDIM);
    transpose_tf32_perm<<<dim3(CDIM / 32, CDIM / 32), 256>>>(Wp, wpt, CDIM, CDIM);

    const int gsm = 2 * STAGE_W * sizeof(float);   // 81920
    cudaFuncSetAttribute(gemm_mma, cudaFuncAttributeMaxDynamicSharedMemorySize, gsm);

    gemm_mma<<<dim3(CDIM / 128, Mq / 128), 256, gsm>>>(xc, wqt, bq, qbuf, Mq, CDIM, CDIM);
    gemm_mma<<<dim3(2 * CDIM / 128, Mkv / 128), 256, gsm>>>(x_c, wkvt, bkv, kvbuf, Mkv, 2 * CDIM, CDIM);

    const int asm_bytes = ATTN_W * sizeof(float);  // 105280
    cudaFuncSetAttribute(attn_tc, cudaFuncAttributeMaxDynamicSharedMemorySize, asm_bytes);
    attn_tc<<<dim3(NHEAD, BnW), 256, asm_bytes>>>(
        qbuf, kvbuf, mask_l, mask_r, nW_ptr, rel, cls_self, cls_up, cls_down, aobuf);

    gemm_mma<<<dim3(CDIM / 128, Mq / 128), 256, gsm>>>(aobuf, wpt, bp, (float*)d_out, Mq, CDIM, CDIM);
}

// round 11
// speedup vs baseline: 1.5893x; 1.0295x over previous
#include <cuda_runtime.h>
#include <cuda_bf16.h>
#include <cstdint>

#define NTOK 65
#define MTOK 129
#define NHEAD 16
#define HDIM 64
#define CDIM 1024

// fp32 intermediates
__device__ float g_q [512 * NTOK * CDIM];
__device__ float g_kv[512 * MTOK * 2 * CDIM];
__device__ float g_ao[512 * NTOK * CDIM];     // raw fp32 (rounded in-GEMM)
// tf32-rounded, k-permuted weights [N][perm(K)]
__device__ float g_wqt [CDIM * CDIM];
__device__ float g_wkvt[2 * CDIM * CDIM];
__device__ float g_wpt [CDIM * CDIM];

__device__ __forceinline__ unsigned f2tf32(float x) {
    unsigned r;
    asm("cvt.rna.tf32.f32 %0, %1;" : "=r"(r) : "f"(x));
    return r;
}
__device__ __forceinline__ void cp16s(uint32_t s, const float* g) {
    asm volatile("cp.async.cg.shared.global [%0], [%1], 16;"
                 :: "r"(s), "l"(g) : "memory");
}
__device__ __forceinline__ uint32_t smem_u32(const void* p) {
    uint32_t a;
    asm("{ .reg .u64 t; cvta.to.shared.u64 t, %1; cvt.u32.u64 %0, t; }"
        : "=r"(a) : "l"(p));
    return a;
}
#define MMA_TF32(acc, a0, a1, a2, a3, b0, b1) \
    asm volatile( \
        "mma.sync.aligned.m16n8k8.row.col.f32.tf32.tf32.f32 " \
        "{%0,%1,%2,%3}, {%4,%5,%6,%7}, {%8,%9}, {%0,%1,%2,%3};" \
        : "+f"((acc)[0]), "+f"((acc)[1]), "+f"((acc)[2]), "+f"((acc)[3]) \
        : "r"(a0), "r"(a1), "r"(a2), "r"(a3), "r"(b0), "r"(b1))

// ---------------------------------------------------------------------------
// W[K][N] fp32 -> Wt[N][perm(K)] tf32-rounded; p(k)=(k&~7)|((k&3)<<1)|((k>>2)&1)
// ---------------------------------------------------------------------------
__global__ __launch_bounds__(256) void transpose_tf32_perm(
    const float* __restrict__ W, float* __restrict__ Wt, int K, int N)
{
    __shared__ float t[32][33];
    const int n0 = blockIdx.x * 32, k0 = blockIdx.y * 32;
    const int tx = threadIdx.x & 31, ty = threadIdx.x >> 5;
    #pragma unroll
    for (int i = 0; i < 4; i++)
        t[ty + 8 * i][tx] = W[(size_t)(k0 + ty + 8 * i) * N + n0 + tx];
    __syncthreads();
    const int pk = (tx & ~7) | ((tx & 3) << 1) | ((tx >> 2) & 1);
    #pragma unroll
    for (int i = 0; i < 4; i++)
        Wt[(size_t)(n0 + ty + 8 * i) * K + k0 + pk] =
            __uint_as_float(f2tf32(t[tx][ty + 8 * i]));
}

// ---------------------------------------------------------------------------
// tf32 mma.sync GEMM: C[M,N] = A[M,K] @ Bt[N,K]^T + bias[N]
// A: RAW fp32 staged via cp.async (stride 36, scalar LDS conflict-free),
//    cvt.rna applied in-register at fragment load.
// B: pre-rounded/permuted weights (stride 40, LDS.64 conflict-free).
// 128x128x32 tile, 8 warps 64x32, 2-stage cp.async, 2 CTA/SM.
// ---------------------------------------------------------------------------
#define AGS 36
#define BGS 40
#define A_WORDS (128 * AGS)            // 4608
#define STAGE_W (A_WORDS + 128 * BGS)  // 9728 words = 38912 B

__global__ __launch_bounds__(256, 2) void gemm_mma(
    const float* __restrict__ A, const float* __restrict__ Bt,
    const float* __restrict__ bias, float* __restrict__ C,
    int M, int N, int K)
{
    extern __shared__ float smg[];     // [2][STAGE_W] = 77824 B

    const int tid  = threadIdx.x;
    const int lane = tid & 31;
    const int warp = tid >> 5;
    const int wm   = warp >> 2;
    const int wn   = warp & 3;
    const int g    = lane >> 2;
    const int t    = lane & 3;

    const int bn = blockIdx.x, bm = blockIdx.y;
    const float* Ag = A  + (size_t)bm * 128 * K;
    const float* Bg = Bt + (size_t)bn * 128 * K;
    const uint32_t sb = smem_u32(smg);

    float acc[4][4][4];
    #pragma unroll
    for (int i = 0; i < 4; i++)
        #pragma unroll
        for (int j = 0; j < 4; j++)
            #pragma unroll
            for (int r = 0; r < 4; r++) acc[i][j][r] = 0.f;

    auto issue = [&](int kt, int s) {
        const uint32_t base = sb + s * (STAGE_W * 4);
        #pragma unroll
        for (int it = 0; it < 8; it++) {
            int idx = tid + it * 256;
            int row = (idx >> 3) & 127, c = idx & 7;
            if (idx < 1024)
                cp16s(base + (row * AGS + c * 4) * 4,
                      Ag + (size_t)row * K + kt + c * 4);
            else
                cp16s(base + (A_WORDS + row * BGS + c * 4) * 4,
                      Bg + (size_t)row * K + kt + c * 4);
        }
        asm volatile("cp.async.commit_group;" ::: "memory");
    };

    issue(0, 0);
    const int NT = K >> 5;
    for (int ti = 0; ti < NT; ti++) {
        const int cur = ti & 1;
        if (ti + 1 < NT) {
            issue((ti + 1) << 5, cur ^ 1);
            asm volatile("cp.async.wait_group 1;" ::: "memory");
        } else {
            asm volatile("cp.async.wait_group 0;" ::: "memory");
        }
        __syncthreads();

        const float* As = smg + cur * STAGE_W;
        const float* Bs = As + A_WORDS;
        #pragma unroll
        for (int ks = 0; ks < 4; ks++) {
            const int kb = ks * 8;
            unsigned af[4][4];
            #pragma unroll
            for (int i = 0; i < 4; i++) {
                int r = wm * 64 + i * 16 + g;
                af[i][0] = f2tf32(As[r * AGS + kb + t]);
                af[i][1] = f2tf32(As[(r + 8) * AGS + kb + t]);
                af[i][2] = f2tf32(As[r * AGS + kb + t + 4]);
                af[i][3] = f2tf32(As[(r + 8) * AGS + kb + t + 4]);
            }
            unsigned bf[4][2];
            #pragma unroll
            for (int j = 0; j < 4; j++) {
                int n = wn * 32 + j * 8 + g;
                uint2 bb = *(const uint2*)(Bs + n * BGS + kb + 2 * t);
                bf[j][0] = bb.x; bf[j][1] = bb.y;
            }
            #pragma unroll
            for (int i = 0; i < 4; i++)
                #pragma unroll
                for (int j = 0; j < 4; j++)
                    MMA_TF32(acc[i][j], af[i][0], af[i][1], af[i][2], af[i][3],
                             bf[j][0], bf[j][1]);
        }
        __syncthreads();
    }

    #pragma unroll
    for (int i = 0; i < 4; i++) {
        int row0 = bm * 128 + wm * 64 + i * 16 + g;
        #pragma unroll
        for (int j = 0; j < 4; j++) {
            int col = bn * 128 + wn * 32 + j * 8 + t * 2;
            float b0 = bias[col], b1 = bias[col + 1];
            float2 v0 = make_float2(acc[i][j][0] + b0, acc[i][j][1] + b1);
            float2 v1 = make_float2(acc[i][j][2] + b0, acc[i][j][3] + b1);
            *(float2*)(C + (size_t)row0 * N + col)       = v0;
            *(float2*)(C + (size_t)(row0 + 8) * N + col) = v1;
        }
    }
}

// ---------------------------------------------------------------------------
// Tensor-core attention v3. One block per (head, window), 256 threads.
// QK^T via mma; softmax SIMT in place (P written k-permuted, pads zeroed);
// V staged via cp.async into dead Q/K smem (stride 72) OVERLAPPED with
// softmax; PV via mma with scalar conflict-free V reads + in-register cvt.
// ---------------------------------------------------------------------------
#define SSTR 136
#define QKS 72
#define OFF_Q (80 * SSTR)                 // 10880
#define OFF_K (OFF_Q + 80 * QKS)          // 16640
#define OFF_TB (OFF_K + 129 * QKS)        // 25928
#define ATTN_W (OFF_TB + 392)             // 26320 words = 105280 B

__global__ __launch_bounds__(256, 2) void attn_tc(
    const float* __restrict__ q, const float* __restrict__ kv,
    const int* __restrict__ mask_l,
    const int* __restrict__ mask_r,
    const int* __restrict__ nW_ptr,
    const float* __restrict__ rel_table,
    const float* __restrict__ cls_self,
    const float* __restrict__ cls_up,
    const float* __restrict__ cls_down,
    float* __restrict__ ao)
{
    const int h = blockIdx.x;
    const int b = blockIdx.y;
    const int tid = threadIdx.x;
    const int lane = tid & 31;
    const int warp = tid >> 5;
    const int g = lane >> 2;
    const int t = lane & 3;

    extern __shared__ float sm[];
    float* Ss = sm;                       // [80][136] scores -> P
    float* Qs = sm + OFF_Q;               // [80][72]
    float* Ks = sm + OFF_K;               // [129][72]
    float* Vs = sm + OFF_Q;               // [129][72] overlay (after QK)
    float* tb = sm + OFF_TB;

    // bias tables
    for (int i = tid; i < 191; i += 256) tb[i] = rel_table[i * NHEAD + h];
    if (tid == 0) tb[191] = cls_self[h];
    for (int i = tid; i < 128; i += 256) tb[192 + i] = cls_up[h * (MTOK - 1) + i];
    for (int i = tid; i < 64; i += 256) tb[320 + i] = cls_down[h * (NTOK - 1) + i];

    // stage Q (65 rows x 8 k-groups), rounded + permuted
    const float* qb = q + (size_t)b * NTOK * CDIM + h * HDIM;
    for (int idx = tid; idx < 65 * 8; idx += 256) {
        int r = idx >> 3, gp = idx & 7;
        const float* p = qb + (size_t)r * CDIM + gp * 8;
        float4 a = *(const float4*)p, c = *(const float4*)(p + 4);
        uint4 w0, w1;
        w0.x = f2tf32(a.x); w0.y = f2tf32(c.x); w0.z = f2tf32(a.y); w0.w = f2tf32(c.y);
        w1.x = f2tf32(a.z); w1.y = f2tf32(c.z); w1.z = f2tf32(a.w); w1.w = f2tf32(c.w);
        *(uint4*)(Qs + r * QKS + gp * 8)     = w0;
        *(uint4*)(Qs + r * QKS + gp * 8 + 4) = w1;
    }
    // stage K (129 rows)
    const float* kb = kv + (size_t)b * MTOK * 2 * CDIM + h * HDIM;
    for (int idx = tid; idx < 129 * 8; idx += 256) {
        int r = idx >> 3, gp = idx & 7;
        const float* p = kb + (size_t)r * 2048 + gp * 8;
        float4 a = *(const float4*)p, c = *(const float4*)(p + 4);
        uint4 w0, w1;
        w0.x = f2tf32(a.x); w0.y = f2tf32(c.x); w0.z = f2tf32(a.y); w0.w = f2tf32(c.y);
        w1.x = f2tf32(a.z); w1.y = f2tf32(c.z); w1.z = f2tf32(a.w); w1.w = f2tf32(c.w);
        *(uint4*)(Ks + r * QKS + gp * 8)     = w0;
        *(uint4*)(Ks + r * QKS + gp * 8 + 4) = w1;
    }
    __syncthreads();

    // ---- QK^T mma: warp owns n-tiles {warp, warp+8} (cols 0..127) ----
    {
        float acc[5][2][4];
        #pragma unroll
        for (int i = 0; i < 5; i++)
            #pragma unroll
            for (int c = 0; c < 2; c++)
                #pragma unroll
                for (int r = 0; r < 4; r++) acc[i][c][r] = 0.f;

        #pragma unroll
        for (int ks = 0; ks < 8; ks++) {
            const int k0 = ks * 8 + 2 * t;
            unsigned af[5][4];
            #pragma unroll
            for (int i = 0; i < 5; i++) {
                int r = i * 16 + g;
                uint2 lo = *(const uint2*)(Qs + r * QKS + k0);
                uint2 hi = *(const uint2*)(Qs + (r + 8) * QKS + k0);
                af[i][0] = lo.x; af[i][2] = lo.y;
                af[i][1] = hi.x; af[i][3] = hi.y;
            }
            #pragma unroll
            for (int c = 0; c < 2; c++) {
                int n = (warp + 8 * c) * 8 + g;
                uint2 bb = *(const uint2*)(Ks + n * QKS + k0);
                #pragma unroll
                for (int i = 0; i < 5; i++)
                    MMA_TF32(acc[i][c], af[i][0], af[i][1], af[i][2], af[i][3],
                             bb.x, bb.y);
            }
        }
        #pragma unroll
        for (int c = 0; c < 2; c++) {
            int col = (warp + 8 * c) * 8 + 2 * t;
            #pragma unroll
            for (int i = 0; i < 5; i++) {
                int q0 = i * 16 + g;
                *(float2*)(Ss + q0 * SSTR + col) =
                    make_float2(acc[i][c][0], acc[i][c][1]);
                *(float2*)(Ss + (q0 + 8) * SSTR + col) =
                    make_float2(acc[i][c][2], acc[i][c][3]);
            }
        }
        // col 128 via SIMT dot (K row 128 hoisted)
        const float k0v = Ks[128 * QKS + lane];
        const float k1v = Ks[128 * QKS + 32 + lane];
        for (int qr = warp; qr < NTOK; qr += 8) {
            float s = fmaf(Qs[qr * QKS + lane], k0v,
                           Qs[qr * QKS + 32 + lane] * k1v);
            #pragma unroll
            for (int o = 16; o; o >>= 1) s += __shfl_xor_sync(~0u, s, o);
            if (lane == 0) Ss[qr * SSTR + 128] = s;
        }
    }
    __syncthreads();   // Q,K dead; Ss holds scores

    // ---- issue V cp.async into overlay (raw fp32, stride 72) ----
    {
        const float* vb = kb + CDIM;
        const uint32_t vbase = smem_u32(Vs);
        for (int idx = tid; idx < 129 * 16; idx += 256) {
            int m = idx >> 4, c = idx & 15;
            cp16s(vbase + (uint32_t)(m * QKS + c * 4) * 4,
                  vb + (size_t)m * 2048 + c * 4);
        }
        asm volatile("cp.async.commit_group;" ::: "memory");
    }

    // ---- softmax + bias + mask (overlapped with V loads) ----
    {
        const int nW = *nW_ptr;
        const int mc = (nW < 2) ? nW : 2;
        const int w = b % nW;
        const bool use_l = (w < mc);
        const bool use_r = (w >= nW - mc);
        const int* ml = mask_l + (size_t)w * NTOK * MTOK;
        const int* mr = mask_r + (size_t)(2 - mc + (w - (nW - mc))) * NTOK * MTOK;
        const float scale = 0.125f;
        const float NEG = -3.402823466e38f;

        for (int qr = warp; qr < NTOK; qr += 8) {
            const int nm = (lane == 0) ? 5 : 4;
            float s[5];
            for (int j = 0; j < nm; j++) {
                const int m = lane + 32 * j;
                float a = Ss[qr * SSTR + m] * scale;
                float bias = (qr == 0)
                    ? ((m == 0) ? tb[191] : tb[192 + m - 1])
                    : ((m == 0) ? tb[320 + qr - 1] : tb[qr - m + 127]);
                a += bias;
                bool msk = false;
                if (use_l) msk = ml[qr * MTOK + m] != 0;
                if (use_r) msk = msk || (mr[qr * MTOK + m] != 0);
                s[j] = msk ? NEG : a;
            }
            float mx = s[0];
            for (int j = 1; j < nm; j++) mx = fmaxf(mx, s[j]);
            #pragma unroll
            for (int o = 16; o; o >>= 1) mx = fmaxf(mx, __shfl_xor_sync(~0u, mx, o));
            float sum = 0.f, p[5];
            for (int j = 0; j < nm; j++) { p[j] = __expf(s[j] - mx); sum += p[j]; }
            #pragma unroll
            for (int o = 16; o; o >>= 1) sum += __shfl_xor_sync(~0u, sum, o);
            const float inv = 1.f / sum;
            __syncwarp();
            for (int j = 0; j < nm; j++) {
                const int m = lane + 32 * j;
                const int pm = (m & ~7) | ((m & 3) << 1) | ((m >> 2) & 1);
                Ss[qr * SSTR + pm] = p[j] * inv;
            }
            if (lane < 7) Ss[qr * SSTR + 129 + lane] = 0.f;   // NaN-safe pad
        }
    }
    asm volatile("cp.async.wait_group 0;" ::: "memory");
    __syncthreads();

    // ---- PV mma: warp owns d-cols warp*8..+7; V scalars from smem ----
    {
        const int wc = warp * 8 + g;
        float acc[5][4];
        #pragma unroll
        for (int i = 0; i < 5; i++)
            #pragma unroll
            for (int r = 0; r < 4; r++) acc[i][r] = 0.f;

        #pragma unroll
        for (int ks = 0; ks < 17; ks++) {
            const int mrow = ks * 8 + t;
            // rows >= 129 hold finite garbage; P pad cols are 0 -> products 0
            const unsigned b0 = f2tf32(Vs[mrow * QKS + wc]);
            const unsigned b1 = f2tf32(Vs[(mrow + 4) * QKS + wc]);
            const int k0 = ks * 8 + 2 * t;
            #pragma unroll
            for (int i = 0; i < 5; i++) {
                int r = i * 16 + g;
                uint2 lo = *(const uint2*)(Ss + r * SSTR + k0);
                uint2 hi = *(const uint2*)(Ss + (r + 8) * SSTR + k0);
                MMA_TF32(acc[i], lo.x, hi.x, lo.y, hi.y, b0, b1);
            }
        }
        // output: raw fp32 (downstream GEMM rounds in-register)
        const int colbase = h * HDIM + warp * 8 + 2 * t;
        #pragma unroll
        for (int i = 0; i < 5; i++) {
            int q0 = i * 16 + g, q1 = q0 + 8;
            if (q0 < NTOK)
                *(float2*)(ao + ((size_t)b * NTOK + q0) * CDIM + colbase) =
                    make_float2(acc[i][0], acc[i][1]);
            if (q1 < NTOK)
                *(float2*)(ao + ((size_t)b * NTOK + q1) * CDIM + colbase) =
                    make_float2(acc[i][2], acc[i][3]);
        }
    }
}

// ---------------------------------------------------------------------------
extern "C" void kernel_launch(void* const* d_in, const int* in_sizes, int n_in,
                              void* d_out, int out_size)
{
    const float* x        = (const float*)d_in[0];
    const float* x_       = (const float*)d_in[1];
    const int*   mask_l   = (const int*)d_in[2];
    const int*   mask_r   = (const int*)d_in[3];
    const int*   nW_ptr   = (const int*)d_in[4];
    const float* Wq       = (const float*)d_in[5];
    const float* bq       = (const float*)d_in[6];
    const float* Wkv      = (const float*)d_in[7];
    const float* bkv      = (const float*)d_in[8];
    const float* Wp       = (const float*)d_in[9];
    const float* bp       = (const float*)d_in[10];
    const float* rel      = (const float*)d_in[11];
    const float* cls_self = (const float*)d_in[12];
    const float* cls_up   = (const float*)d_in[13];
    const float* cls_down = (const float*)d_in[14];

    const int BnW = in_sizes[0] / (NTOK * CDIM);   // 512
    const int Mq  = BnW * NTOK;                    // 33280
    const int Mkv = BnW * MTOK;                    // 66048

    float *qbuf, *kvbuf, *aobuf, *wqt, *wkvt, *wpt;
    cudaGetSymbolAddress((void**)&qbuf,  g_q);
    cudaGetSymbolAddress((void**)&kvbuf, g_kv);
    cudaGetSymbolAddress((void**)&aobuf, g_ao);
    cudaGetSymbolAddress((void**)&wqt,   g_wqt);
    cudaGetSymbolAddress((void**)&wkvt,  g_wkvt);
    cudaGetSymbolAddress((void**)&wpt,   g_wpt);

    // weights -> [N][perm(K)] tf32-rounded (activations stay raw)
    transpose_tf32_perm<<<dim3(CDIM / 32, CDIM / 32), 256>>>(Wq, wqt, CDIM, CDIM);
    transpose_tf32_perm<<<dim3(2 * CDIM / 32, CDIM / 32), 256>>>(Wkv, wkvt, CDIM, 2 * CDIM);
    transpose_tf32_perm<<<dim3(CDIM / 32, CDIM / 32), 256>>>(Wp, wpt, CDIM, CDIM);

    const int gsm = 2 * STAGE_W * sizeof(float);   // 77824
    cudaFuncSetAttribute(gemm_mma, cudaFuncAttributeMaxDynamicSharedMemorySize, gsm);

    gemm_mma<<<dim3(CDIM / 128, Mq / 128), 256, gsm>>>(x, wqt, bq, qbuf, Mq, CDIM, CDIM);
    gemm_mma<<<dim3(2 * CDIM / 128, Mkv / 128), 256, gsm>>>(x_, wkvt, bkv, kvbuf, Mkv, 2 * CDIM, CDIM);

    const int asm_bytes = ATTN_W * sizeof(float);  // 105280
    cudaFuncSetAttribute(attn_tc, cudaFuncAttributeMaxDynamicSharedMemorySize, asm_bytes);
    attn_tc<<<dim3(NHEAD, BnW), 256, asm_bytes>>>(
        qbuf, kvbuf, mask_l, mask_r, nW_ptr, rel, cls_self, cls_up, cls_down, aobuf);

    gemm_mma<<<dim3(CDIM / 128, Mq / 128), 256, gsm>>>(aobuf, wpt, bp, (float*)d_out, Mq, CDIM, CDIM);
}